// round 1
// baseline (speedup 1.0000x reference)
#include <cuda_runtime.h>
#include <cuda_bf16.h>

#define NN 8192
#define TEMPER 0.2f

// Scratch (static __device__ arrays per harness rules)
static __device__ __nv_bfloat16 g_Q[(size_t)NN * NN];   // 128 MB bf16 Q for iterations
static __device__ float g_colAcc[NN];
static __device__ float g_V[NN];
static __device__ float g_U[NN];
static __device__ unsigned int g_minBits;
static __device__ double g_sum;
static __device__ double g_sumsq;
static __device__ float g_minv;
static __device__ float g_kscale;

// ---------------------------------------------------------------- init
__global__ void k_init() {
    int i = blockIdx.x * blockDim.x + threadIdx.x;
    if (i < NN) g_colAcc[i] = 0.0f;
    if (i == 0) {
        g_minBits = 0x7f800000u;  // +inf
        g_sum = 0.0;
        g_sumsq = 0.0;
    }
}

// ---------------------------------------------------------------- reduce: min / sum / sumsq
__global__ void __launch_bounds__(256) k_reduce(const float* __restrict__ c) {
    const size_t total4 = (size_t)NN * NN / 4;
    const size_t stride = (size_t)gridDim.x * blockDim.x;
    double s = 0.0, ss = 0.0;
    float mn = 3.402823466e38f;
    for (size_t i = (size_t)blockIdx.x * blockDim.x + threadIdx.x; i < total4; i += stride) {
        float4 v = reinterpret_cast<const float4*>(c)[i];
        float cs  = (v.x + v.y) + (v.z + v.w);
        float css = fmaf(v.x, v.x, fmaf(v.y, v.y, fmaf(v.z, v.z, v.w * v.w)));
        s  += (double)cs;
        ss += (double)css;
        mn = fminf(mn, fminf(fminf(v.x, v.y), fminf(v.z, v.w)));
    }
    for (int o = 16; o > 0; o >>= 1) {
        s  += __shfl_down_sync(0xffffffffu, s, o);
        ss += __shfl_down_sync(0xffffffffu, ss, o);
        mn = fminf(mn, __shfl_down_sync(0xffffffffu, mn, o));
    }
    __shared__ double sh_s[8], sh_ss[8];
    __shared__ float sh_m[8];
    int warp = threadIdx.x >> 5, lane = threadIdx.x & 31;
    if (lane == 0) { sh_s[warp] = s; sh_ss[warp] = ss; sh_m[warp] = mn; }
    __syncthreads();
    if (threadIdx.x < 8) {
        s = sh_s[threadIdx.x]; ss = sh_ss[threadIdx.x]; mn = sh_m[threadIdx.x];
        for (int o = 4; o > 0; o >>= 1) {
            s  += __shfl_down_sync(0xffu, s, o);
            ss += __shfl_down_sync(0xffu, ss, o);
            mn = fminf(mn, __shfl_down_sync(0xffu, mn, o));
        }
        if (threadIdx.x == 0) {
            atomicAdd(&g_sum, s);
            atomicAdd(&g_sumsq, ss);
            atomicMin(&g_minBits, __float_as_uint(mn));
        }
    }
}

// ---------------------------------------------------------------- scalar finalize
__global__ void k_scalars() {
    double n = (double)NN * (double)NN;
    double var = (g_sumsq - g_sum * g_sum / n) / (n - 1.0);
    float stdv = (float)sqrt(var);
    g_minv = __uint_as_float(g_minBits);
    g_kscale = 1.0f / (stdv * TEMPER);
}

// ---------------------------------------------------------------- build Q (bf16) + colsum -> V1
// grid (8, 64): blockIdx.x = 1024-col chunk, blockIdx.y = 128-row chunk; 4 cols/thread
__global__ void __launch_bounds__(256) k_build(const float* __restrict__ c) {
    const float minv = g_minv, kk = g_kscale;
    int col0 = (blockIdx.x * 256 + threadIdx.x) * 4;
    int row0 = blockIdx.y * 128;
    float a0 = 0.f, a1 = 0.f, a2 = 0.f, a3 = 0.f;
    for (int r = 0; r < 128; ++r) {
        size_t base = (size_t)(row0 + r) * NN + col0;
        float4 v = *reinterpret_cast<const float4*>(c + base);
        float q0 = __expf((minv - v.x) * kk);
        float q1 = __expf((minv - v.y) * kk);
        float q2 = __expf((minv - v.z) * kk);
        float q3 = __expf((minv - v.w) * kk);
        a0 += q0; a1 += q1; a2 += q2; a3 += q3;
        __nv_bfloat162 p0 = __floats2bfloat162_rn(q0, q1);
        __nv_bfloat162 p1 = __floats2bfloat162_rn(q2, q3);
        uint2 w;
        w.x = *reinterpret_cast<unsigned int*>(&p0);
        w.y = *reinterpret_cast<unsigned int*>(&p1);
        *reinterpret_cast<uint2*>(g_Q + base) = w;
    }
    atomicAdd(&g_colAcc[col0 + 0], a0);
    atomicAdd(&g_colAcc[col0 + 1], a1);
    atomicAdd(&g_colAcc[col0 + 2], a2);
    atomicAdd(&g_colAcc[col0 + 3], a3);
}

// ---------------------------------------------------------------- V = B / colAcc ; colAcc = 0
__global__ void k_vfin(const float* __restrict__ B) {
    int j = blockIdx.x * blockDim.x + threadIdx.x;
    if (j < NN) {
        g_V[j] = B[j] / g_colAcc[j];
        g_colAcc[j] = 0.0f;
    }
}

__device__ __forceinline__ float dot8(uint4 raw, float4 va, float4 vb) {
    float2 f0 = __bfloat1622float2(*reinterpret_cast<__nv_bfloat162*>(&raw.x));
    float2 f1 = __bfloat1622float2(*reinterpret_cast<__nv_bfloat162*>(&raw.y));
    float2 f2 = __bfloat1622float2(*reinterpret_cast<__nv_bfloat162*>(&raw.z));
    float2 f3 = __bfloat1622float2(*reinterpret_cast<__nv_bfloat162*>(&raw.w));
    float r = f0.x * va.x;
    r = fmaf(f0.y, va.y, r);
    r = fmaf(f1.x, va.z, r);
    r = fmaf(f1.y, va.w, r);
    r = fmaf(f2.x, vb.x, r);
    r = fmaf(f2.y, vb.y, r);
    r = fmaf(f3.x, vb.z, r);
    r = fmaf(f3.y, vb.w, r);
    return r;
}

// ---------------------------------------------------------------- U = A / (Q~ V)
// 256 blocks, 8 warps/block, each warp handles 4 rows at a time (V reuse from SMEM)
__global__ void __launch_bounds__(256) k_rowmv(const float* __restrict__ A) {
    __shared__ float sV[NN];
    int tid = threadIdx.x;
#pragma unroll
    for (int i = 0; i < 8; ++i)
        reinterpret_cast<float4*>(sV)[tid + i * 256] =
            reinterpret_cast<const float4*>(g_V)[tid + i * 256];
    __syncthreads();
    int warp = tid >> 5, lane = tid & 31;
    int row0 = blockIdx.x * 32 + warp * 4;
    float s0 = 0.f, s1 = 0.f, s2 = 0.f, s3 = 0.f;
    const __nv_bfloat16* q0 = g_Q + (size_t)row0 * NN;
#pragma unroll 2
    for (int k = 0; k < 32; ++k) {
        int j = lane * 8 + k * 256;
        float4 va = *reinterpret_cast<const float4*>(sV + j);
        float4 vb = *reinterpret_cast<const float4*>(sV + j + 4);
        uint4 r0 = *reinterpret_cast<const uint4*>(q0 + j);
        uint4 r1 = *reinterpret_cast<const uint4*>(q0 + NN + j);
        uint4 r2 = *reinterpret_cast<const uint4*>(q0 + 2 * NN + j);
        uint4 r3 = *reinterpret_cast<const uint4*>(q0 + 3 * NN + j);
        s0 += dot8(r0, va, vb);
        s1 += dot8(r1, va, vb);
        s2 += dot8(r2, va, vb);
        s3 += dot8(r3, va, vb);
    }
    for (int o = 16; o > 0; o >>= 1) {
        s0 += __shfl_down_sync(0xffffffffu, s0, o);
        s1 += __shfl_down_sync(0xffffffffu, s1, o);
        s2 += __shfl_down_sync(0xffffffffu, s2, o);
        s3 += __shfl_down_sync(0xffffffffu, s3, o);
    }
    if (lane == 0) {
        g_U[row0 + 0] = __ldg(A + row0 + 0) / s0;
        g_U[row0 + 1] = __ldg(A + row0 + 1) / s1;
        g_U[row0 + 2] = __ldg(A + row0 + 2) / s2;
        g_U[row0 + 3] = __ldg(A + row0 + 3) / s3;
    }
}

// ---------------------------------------------------------------- colAcc += Q~^T U (atomics)
// grid (4, 64): 2048 cols x 128 rows per block; 8 cols/thread
__global__ void __launch_bounds__(256) k_colmv() {
    __shared__ float sU[128];
    int tid = threadIdx.x;
    int col0 = blockIdx.x * 2048 + tid * 8;
    int row0 = blockIdx.y * 128;
    if (tid < 128) sU[tid] = g_U[row0 + tid];
    __syncthreads();
    float a0 = 0.f, a1 = 0.f, a2 = 0.f, a3 = 0.f, a4 = 0.f, a5 = 0.f, a6 = 0.f, a7 = 0.f;
    const __nv_bfloat16* qp = g_Q + (size_t)row0 * NN + col0;
#pragma unroll 4
    for (int r = 0; r < 128; ++r) {
        float u = sU[r];
        uint4 raw = *reinterpret_cast<const uint4*>(qp + (size_t)r * NN);
        float2 f0 = __bfloat1622float2(*reinterpret_cast<__nv_bfloat162*>(&raw.x));
        float2 f1 = __bfloat1622float2(*reinterpret_cast<__nv_bfloat162*>(&raw.y));
        float2 f2 = __bfloat1622float2(*reinterpret_cast<__nv_bfloat162*>(&raw.z));
        float2 f3 = __bfloat1622float2(*reinterpret_cast<__nv_bfloat162*>(&raw.w));
        a0 = fmaf(f0.x, u, a0);
        a1 = fmaf(f0.y, u, a1);
        a2 = fmaf(f1.x, u, a2);
        a3 = fmaf(f1.y, u, a3);
        a4 = fmaf(f2.x, u, a4);
        a5 = fmaf(f2.y, u, a5);
        a6 = fmaf(f3.x, u, a6);
        a7 = fmaf(f3.y, u, a7);
    }
    atomicAdd(&g_colAcc[col0 + 0], a0);
    atomicAdd(&g_colAcc[col0 + 1], a1);
    atomicAdd(&g_colAcc[col0 + 2], a2);
    atomicAdd(&g_colAcc[col0 + 3], a3);
    atomicAdd(&g_colAcc[col0 + 4], a4);
    atomicAdd(&g_colAcc[col0 + 5], a5);
    atomicAdd(&g_colAcc[col0 + 6], a6);
    atomicAdd(&g_colAcc[col0 + 7], a7);
}

// ---------------------------------------------------------------- final: exact Q, fused U10, write T
// persistent blocks, row per block-iteration; exact fp32 Q recomputed from cdist
__global__ void __launch_bounds__(256) k_final(const float* __restrict__ c,
                                               const float* __restrict__ A,
                                               float* __restrict__ out) {
    __shared__ float sV[NN];
    __shared__ float sred[8];
    __shared__ float sbc;
    int tid = threadIdx.x;
#pragma unroll
    for (int i = 0; i < 8; ++i)
        reinterpret_cast<float4*>(sV)[tid + i * 256] =
            reinterpret_cast<const float4*>(g_V)[tid + i * 256];
    __syncthreads();
    const float minv = g_minv, kk = g_kscale;
    for (int row = blockIdx.x; row < NN; row += gridDim.x) {
        const float4* crow = reinterpret_cast<const float4*>(c + (size_t)row * NN);
        float4 qv[8];
        float s = 0.f;
#pragma unroll
        for (int k = 0; k < 8; ++k) {
            int j = tid * 4 + k * 1024;
            float4 v  = crow[tid + k * 256];
            float4 vv = *reinterpret_cast<const float4*>(sV + j);
            float q0 = __expf((minv - v.x) * kk) * vv.x;
            float q1 = __expf((minv - v.y) * kk) * vv.y;
            float q2 = __expf((minv - v.z) * kk) * vv.z;
            float q3 = __expf((minv - v.w) * kk) * vv.w;
            qv[k].x = q0; qv[k].y = q1; qv[k].z = q2; qv[k].w = q3;
            s += (q0 + q1) + (q2 + q3);
        }
        for (int o = 16; o > 0; o >>= 1)
            s += __shfl_down_sync(0xffffffffu, s, o);
        if ((tid & 31) == 0) sred[tid >> 5] = s;
        __syncthreads();
        if (tid < 32) {
            float t = (tid < 8) ? sred[tid] : 0.f;
            for (int o = 4; o > 0; o >>= 1)
                t += __shfl_down_sync(0xffffffffu, t, o);
            if (tid == 0) sbc = __ldg(A + row) / t;
        }
        __syncthreads();
        float scale = sbc;
        float4* orow = reinterpret_cast<float4*>(out + (size_t)row * NN);
#pragma unroll
        for (int k = 0; k < 8; ++k) {
            float4 w = qv[k];
            w.x *= scale; w.y *= scale; w.z *= scale; w.w *= scale;
            orow[tid + k * 256] = w;
        }
        __syncthreads();  // protect sred/sbc reuse next row
    }
}

// ---------------------------------------------------------------- launch
extern "C" void kernel_launch(void* const* d_in, const int* in_sizes, int n_in,
                              void* d_out, int out_size) {
    const float* cdist = (const float*)d_in[0];
    const float* A     = (const float*)d_in[1];
    const float* B     = (const float*)d_in[2];
    float* out = (float*)d_out;

    k_init<<<32, 256>>>();
    k_reduce<<<1184, 256>>>(cdist);
    k_scalars<<<1, 1>>>();
    k_build<<<dim3(8, 64), 256>>>(cdist);   // writes Q~ (bf16), colsum -> colAcc
    k_vfin<<<32, 256>>>(B);                 // V1 = B / colsum(Q)
    k_rowmv<<<256, 256>>>(A);               // U1 = A / (Q~ V1)
    for (int k = 2; k <= 10; ++k) {
        k_colmv<<<dim3(4, 64), 256>>>();    // colAcc = Q~^T U_{k-1}
        k_vfin<<<32, 256>>>(B);             // V_k = B / colAcc
        if (k <= 9)
            k_rowmv<<<256, 256>>>(A);       // U_k = A / (Q~ V_k)
    }
    // U10 fused: exact fp32 Q recomputed, T = (A_i / (Q V10)_i) * Q_ij * V10_j
    k_final<<<444, 256>>>(cdist, A, out);
}